// round 3
// baseline (speedup 1.0000x reference)
#include <cuda_runtime.h>
#include <cstdint>
#include <cfloat>

// Problem constants (dataset-fixed; T derived at launch from in_sizes)
#define C_CL   8
#define E_EX   8
#define D_DIM  4096
#define NTOT   (C_CL * E_EX)   // 64 output slots
#define MAX_T  8192

// Scratch (no allocs allowed)
__device__ int g_cnt[C_CL];
__device__ int g_cluster[MAX_T];           // chosen cluster per token
__device__ int g_bucket[C_CL * MAX_T];     // gapped per-cluster token lists
__device__ int g_order[MAX_T];             // compacted cluster-major token order

__global__ void zero_cnt_kernel() {
    if (threadIdx.x < C_CL) g_cnt[threadIdx.x] = 0;
}

// Read expert_ids[i] robustly whether the harness delivered int32 or int64.
// expert_ids content is arange(64): int32 view element 1 is 1 for int32
// delivery, 0 for int64 (little-endian: [0,0, 1,0, 2,0, ...]).
__device__ __forceinline__ int read_eid(const void* p, int i) {
    const int* p32 = (const int*)p;
    if (__ldg(p32 + 1) == 0) {
        // int64 layout
        return (int)__ldg(((const long long*)p) + i);
    }
    return __ldg(p32 + i);
}

// ============================================================================
// Pass A: cluster logits + argmax + bucket scatter.
// Warp = 4 tokens; 8 lanes/token so one token-iter covers one full 128B line
// of x, and the 8 weight float4s cover exactly one 128B line (broadcast
// across the 4 token groups).
// ============================================================================
__global__ void __launch_bounds__(256) cluster_kernel(
    const float* __restrict__ x,
    const float* __restrict__ Wc,
    int T)
{
    const int gwarp = (blockIdx.x * blockDim.x + threadIdx.x) >> 5;
    const int lane  = threadIdx.x & 31;
    const int sub   = lane & 7;       // element-slice within token
    const int tq    = lane >> 3;      // token within warp (0..3)
    const int tok   = gwarp * 4 + tq;

    const float4* xr = reinterpret_cast<const float4*>(x + (size_t)tok * D_DIM);

    float acc[C_CL];
#pragma unroll
    for (int c = 0; c < C_CL; ++c) acc[c] = 0.0f;

#pragma unroll 4
    for (int k = 0; k < D_DIM / 32; ++k) {
        const int f4 = k * 8 + sub;               // float4 index within row
        float4 xv = __ldg(xr + f4);
#pragma unroll
        for (int c = 0; c < C_CL; ++c) {
            float4 wv = __ldg(reinterpret_cast<const float4*>(Wc + c * D_DIM) + f4);
            acc[c] = fmaf(xv.x, wv.x, acc[c]);
            acc[c] = fmaf(xv.y, wv.y, acc[c]);
            acc[c] = fmaf(xv.z, wv.z, acc[c]);
            acc[c] = fmaf(xv.w, wv.w, acc[c]);
        }
    }

    // Butterfly-reduce across the 8 lanes of each token (xor 1,2,4).
#pragma unroll
    for (int s = 1; s <= 4; s <<= 1) {
#pragma unroll
        for (int c = 0; c < C_CL; ++c)
            acc[c] += __shfl_xor_sync(0xffffffffu, acc[c], s);
    }

    if (sub == 0) {
        float best = acc[0];
        int bi = 0;
#pragma unroll
        for (int c = 1; c < C_CL; ++c) {
            if (acc[c] > best) { best = acc[c]; bi = c; }  // strict > = first-max
        }
        g_cluster[tok] = bi;
        int r = atomicAdd(&g_cnt[bi], 1);
        g_bucket[bi * MAX_T + r] = tok;
    }
}

// ============================================================================
// Middle: compact gapped buckets into cluster-major flat order.
// ============================================================================
__global__ void __launch_bounds__(256) order_kernel() {
    __shared__ int base[C_CL];
    if (threadIdx.x == 0) {
        int b = 0;
        for (int c = 0; c < C_CL; ++c) { base[c] = b; b += g_cnt[c]; }
    }
    __syncthreads();
    for (int c = 0; c < C_CL; ++c) {
        const int n = g_cnt[c];
        const int b = base[c];
        for (int i = threadIdx.x; i < n; i += 256)
            g_order[b + i] = g_bucket[c * MAX_T + i];
    }
}

// ============================================================================
// Pass B: expert logits for the selected cluster + scatter into output row.
// Tokens come from g_order (cluster-major), so the 4 tokens in a warp almost
// always share a cluster -> expert-weight lines are broadcast. Correctness
// does NOT depend on the ordering: each token uses its own g_cluster[tok].
// ============================================================================
__global__ void __launch_bounds__(256) expert_kernel(
    const float* __restrict__ x,
    const float* __restrict__ We,
    const void* __restrict__ eids,
    float* __restrict__ out,
    int T)
{
    const int gwarp = (blockIdx.x * blockDim.x + threadIdx.x) >> 5;
    const int lane  = threadIdx.x & 31;
    const int sub   = lane & 7;
    const int tq    = lane >> 3;
    const int p     = gwarp * 4 + tq;     // position in compacted order

    const int tok = g_order[p];
    const int c   = g_cluster[tok];

    const float4* xr = reinterpret_cast<const float4*>(x + (size_t)tok * D_DIM);
    const float*  wb = We + (size_t)c * (E_EX * D_DIM);

    float acc[E_EX];
#pragma unroll
    for (int e = 0; e < E_EX; ++e) acc[e] = 0.0f;

#pragma unroll 4
    for (int k = 0; k < D_DIM / 32; ++k) {
        const int f4 = k * 8 + sub;
        float4 xv = __ldg(xr + f4);
#pragma unroll
        for (int e = 0; e < E_EX; ++e) {
            float4 wv = __ldg(reinterpret_cast<const float4*>(wb + e * D_DIM) + f4);
            acc[e] = fmaf(xv.x, wv.x, acc[e]);
            acc[e] = fmaf(xv.y, wv.y, acc[e]);
            acc[e] = fmaf(xv.z, wv.z, acc[e]);
            acc[e] = fmaf(xv.w, wv.w, acc[e]);
        }
    }

#pragma unroll
    for (int s = 1; s <= 4; s <<= 1) {
#pragma unroll
        for (int e = 0; e < E_EX; ++e)
            acc[e] += __shfl_xor_sync(0xffffffffu, acc[e], s);
    }

    // Global expert slots for this cluster (dtype-robust read).
    int eid[E_EX];
#pragma unroll
    for (int e = 0; e < E_EX; ++e)
        eid[e] = read_eid(eids, c * E_EX + e);

    // Each of the 8 lanes of this token writes 8 contiguous output columns.
    float v[8];
#pragma unroll
    for (int k2 = 0; k2 < 8; ++k2) {
        const int col = sub * 8 + k2;
        float val = -FLT_MAX;              // == jnp.finfo(float32).min
#pragma unroll
        for (int e = 0; e < E_EX; ++e)
            val = (eid[e] == col) ? acc[e] : val;
        v[k2] = val;
    }
    float4* o = reinterpret_cast<float4*>(out + (size_t)tok * NTOT + sub * 8);
    o[0] = make_float4(v[0], v[1], v[2], v[3]);
    o[1] = make_float4(v[4], v[5], v[6], v[7]);
}

extern "C" void kernel_launch(void* const* d_in, const int* in_sizes, int n_in,
                              void* d_out, int out_size) {
    const float* x    = (const float*)d_in[0];
    const float* Wc   = (const float*)d_in[1];
    const float* We   = (const float*)d_in[2];
    const void*  eids = d_in[3];
    float*       out  = (float*)d_out;

    const int D = in_sizes[2] / in_sizes[3];     // 4096
    const int T = in_sizes[0] / D;               // 8192
    (void)n_in; (void)out_size;

    zero_cnt_kernel<<<1, 32>>>();

    const int warps  = T / 4;            // 4 tokens per warp
    const int blocks = warps / 8;        // 256 threads = 8 warps per block
    cluster_kernel<<<blocks, 256>>>(x, Wc, T);
    order_kernel<<<1, 256>>>();
    expert_kernel<<<blocks, 256>>>(x, We, eids, out, T);
}

// round 4
// speedup vs baseline: 2.0288x; 2.0288x over previous
#include <cuda_runtime.h>
#include <cstdint>
#include <cfloat>

// Problem constants (dataset-fixed; T derived at launch from in_sizes)
#define C_CL   8
#define E_EX   8
#define D_DIM  4096
#define NTOT   (C_CL * E_EX)   // 64 output slots
#define MAX_T  8192
#define NSPLIT 4               // D-dim splits per token-group (occupancy lever)

// Scratch (no allocs allowed)
__device__ int g_cnt[C_CL];
__device__ int g_cluster[MAX_T];           // chosen cluster per token
__device__ int g_bucket[C_CL * MAX_T];     // gapped per-cluster token lists
__device__ int g_order[MAX_T];             // compacted cluster-major token order

__global__ void zero_cnt_kernel() {
    if (threadIdx.x < C_CL) g_cnt[threadIdx.x] = 0;
}

// Read expert_ids[i] robustly whether the harness delivered int32 or int64.
// Content is arange(64): int32-view element 1 is 1 for int32 delivery,
// 0 for int64 (little-endian [0,0, 1,0, 2,0, ...]).
__device__ __forceinline__ int read_eid(const void* p, int i) {
    const int* p32 = (const int*)p;
    if (__ldg(p32 + 1) == 0) return (int)__ldg(((const long long*)p) + i);
    return __ldg(p32 + i);
}

// ============================================================================
// Pass A: cluster logits + argmax + bucket scatter.
// Block = 8 warps = 2 token-groups x 4 D-splits. Each warp: 4 tokens x 8
// lanes/token x 1024 dims. Layout is L1-optimal: per warp-iter the 4 x-float4
// groups each cover one 128B line, and the 8 weight float4s per cluster cover
// exactly one broadcast line.
// ============================================================================
__global__ void __launch_bounds__(256) cluster_kernel(
    const float* __restrict__ x,
    const float* __restrict__ Wc)
{
    __shared__ float s_part[2][NSPLIT][4][8];   // [tg_local][split][tok][c]

    const int w    = threadIdx.x >> 5;
    const int lane = threadIdx.x & 31;
    const int tgl  = w >> 2;            // token-group within block (0..1)
    const int s    = w & 3;             // D-split (0..3)
    const int sub  = lane & 7;          // element-slice within token
    const int tq   = lane >> 3;         // token within warp (0..3)
    const int tok  = (blockIdx.x * 2 + tgl) * 4 + tq;

    const float4* xr = reinterpret_cast<const float4*>(x + (size_t)tok * D_DIM);
    const int base = s * 256;           // float4 offset of this split

    float acc[C_CL];
#pragma unroll
    for (int c = 0; c < C_CL; ++c) acc[c] = 0.0f;

#pragma unroll 4
    for (int k = 0; k < 32; ++k) {
        const int f4 = base + k * 8 + sub;
        float4 xv = __ldg(xr + f4);
#pragma unroll
        for (int c = 0; c < C_CL; ++c) {
            float4 wv = __ldg(reinterpret_cast<const float4*>(Wc + c * D_DIM) + f4);
            acc[c] = fmaf(xv.x, wv.x, acc[c]);
            acc[c] = fmaf(xv.y, wv.y, acc[c]);
            acc[c] = fmaf(xv.z, wv.z, acc[c]);
            acc[c] = fmaf(xv.w, wv.w, acc[c]);
        }
    }

    // Reduce across the 8 lanes of each token.
#pragma unroll
    for (int d = 1; d <= 4; d <<= 1)
#pragma unroll
        for (int c = 0; c < C_CL; ++c)
            acc[c] += __shfl_xor_sync(0xffffffffu, acc[c], d);

    // Lane sub==c contributes acc[c] (static-indexed, no spill).
#pragma unroll
    for (int c = 0; c < C_CL; ++c)
        if (sub == c) s_part[tgl][s][tq][c] = acc[c];
    __syncthreads();

    // Combine splits + argmax: 64 threads = 2 tg x 4 tok x 8 c.
    if (threadIdx.x < 64) {
        const int tgl2 = threadIdx.x >> 5;
        const int tq2  = (threadIdx.x >> 3) & 3;
        const int c    = threadIdx.x & 7;
        float v = s_part[tgl2][0][tq2][c] + s_part[tgl2][1][tq2][c]
                + s_part[tgl2][2][tq2][c] + s_part[tgl2][3][tq2][c];
        int bi = c;
#pragma unroll
        for (int d = 1; d <= 4; d <<= 1) {
            float vo = __shfl_xor_sync(0xffffffffu, v, d);
            int   io = __shfl_xor_sync(0xffffffffu, bi, d);
            if (vo > v || (vo == v && io < bi)) { v = vo; bi = io; }  // first-max
        }
        if (c == 0) {
            const int t = (blockIdx.x * 2 + tgl2) * 4 + tq2;
            g_cluster[t] = bi;
            int r = atomicAdd(&g_cnt[bi], 1);
            g_bucket[bi * MAX_T + r] = t;
        }
    }
}

// ============================================================================
// Middle: compact gapped buckets into cluster-major flat order.
// ============================================================================
__global__ void __launch_bounds__(256) order_kernel() {
    __shared__ int base[C_CL];
    if (threadIdx.x == 0) {
        int b = 0;
        for (int c = 0; c < C_CL; ++c) { base[c] = b; b += g_cnt[c]; }
    }
    __syncthreads();
    for (int c = 0; c < C_CL; ++c) {
        const int n = g_cnt[c];
        const int b = base[c];
        for (int i = threadIdx.x; i < n; i += 256)
            g_order[b + i] = g_bucket[c * MAX_T + i];
    }
}

// ============================================================================
// Pass B: expert logits for the selected cluster + scatter into output row.
// Tokens taken cluster-major from g_order so the 4 tokens in a warp share
// the expert-weight lines (except rare bucket-boundary warps). Same D-split
// structure as pass A; epilogue scatters into the 64-wide output row.
// ============================================================================
__global__ void __launch_bounds__(256) expert_kernel(
    const float* __restrict__ x,
    const float* __restrict__ We,
    const void* __restrict__ eids,
    float* __restrict__ out)
{
    __shared__ float s_part[2][NSPLIT][4][8];   // [tg_local][split][tok][e]
    __shared__ float s_logit[8][8];             // [tok_local][e]
    __shared__ int   s_eid[8][8];               // [tok_local][e]
    __shared__ int   s_tok[8];
    __shared__ int   s_cl[8];

    const int w    = threadIdx.x >> 5;
    const int lane = threadIdx.x & 31;
    const int tgl  = w >> 2;
    const int s    = w & 3;
    const int sub  = lane & 7;
    const int tq   = lane >> 3;
    const int tl   = tgl * 4 + tq;                       // token slot in block (0..7)
    const int p    = blockIdx.x * 8 + tl;                // position in compacted order

    const int tok = __ldg(&g_order[p]);
    const int c   = g_cluster[tok];
    if (s == 0 && sub == 0) { s_tok[tl] = tok; s_cl[tl] = c; }

    const float4* xr = reinterpret_cast<const float4*>(x + (size_t)tok * D_DIM);
    const float*  wb = We + (size_t)c * (E_EX * D_DIM);
    const int base = s * 256;

    float acc[E_EX];
#pragma unroll
    for (int e = 0; e < E_EX; ++e) acc[e] = 0.0f;

#pragma unroll 4
    for (int k = 0; k < 32; ++k) {
        const int f4 = base + k * 8 + sub;
        float4 xv = __ldg(xr + f4);
#pragma unroll
        for (int e = 0; e < E_EX; ++e) {
            float4 wv = __ldg(reinterpret_cast<const float4*>(wb + e * D_DIM) + f4);
            acc[e] = fmaf(xv.x, wv.x, acc[e]);
            acc[e] = fmaf(xv.y, wv.y, acc[e]);
            acc[e] = fmaf(xv.z, wv.z, acc[e]);
            acc[e] = fmaf(xv.w, wv.w, acc[e]);
        }
    }

#pragma unroll
    for (int d = 1; d <= 4; d <<= 1)
#pragma unroll
        for (int e = 0; e < E_EX; ++e)
            acc[e] += __shfl_xor_sync(0xffffffffu, acc[e], d);

#pragma unroll
    for (int e = 0; e < E_EX; ++e)
        if (sub == e) s_part[tgl][s][tq][e] = acc[e];
    __syncthreads();

    // Combine splits: 64 threads = 8 tok x 8 e; also fetch expert ids.
    if (threadIdx.x < 64) {
        const int tl2 = threadIdx.x >> 3;
        const int e   = threadIdx.x & 7;
        const int tgl2 = tl2 >> 2, tq2 = tl2 & 3;
        s_logit[tl2][e] = s_part[tgl2][0][tq2][e] + s_part[tgl2][1][tq2][e]
                        + s_part[tgl2][2][tq2][e] + s_part[tgl2][3][tq2][e];
        s_eid[tl2][e] = read_eid(eids, s_cl[tl2] * E_EX + e);
    }
    __syncthreads();

    // Scatter: 128 threads write 8 tokens x 16 float4 (full 64-col rows).
    if (threadIdx.x < 128) {
        const int tl3 = threadIdx.x >> 4;
        const int q   = threadIdx.x & 15;
        const int tok3 = s_tok[tl3];
        float v[4];
#pragma unroll
        for (int j = 0; j < 4; ++j) {
            const int col = q * 4 + j;
            float val = -FLT_MAX;              // == jnp.finfo(float32).min
#pragma unroll
            for (int e = 0; e < E_EX; ++e)
                val = (s_eid[tl3][e] == col) ? s_logit[tl3][e] : val;
            v[j] = val;
        }
        reinterpret_cast<float4*>(out + (size_t)tok3 * NTOT)[q] =
            make_float4(v[0], v[1], v[2], v[3]);
    }
}

extern "C" void kernel_launch(void* const* d_in, const int* in_sizes, int n_in,
                              void* d_out, int out_size) {
    const float* x    = (const float*)d_in[0];
    const float* Wc   = (const float*)d_in[1];
    const float* We   = (const float*)d_in[2];
    const void*  eids = d_in[3];
    float*       out  = (float*)d_out;

    const int D = in_sizes[2] / in_sizes[3];     // 4096
    const int T = in_sizes[0] / D;               // 8192
    (void)n_in; (void)out_size;

    zero_cnt_kernel<<<1, 32>>>();

    const int blocks = T / 8;            // 8 tokens per block (2 tg x 4 splits)
    cluster_kernel<<<blocks, 256>>>(x, Wc);
    order_kernel<<<1, 256>>>();
    expert_kernel<<<blocks, 256>>>(x, We, eids, out);
}

// round 5
// speedup vs baseline: 2.7001x; 1.3309x over previous
#include <cuda_runtime.h>
#include <cstdint>
#include <cfloat>

// Problem constants (dataset-fixed; T derived at launch from in_sizes)
#define C_CL   8
#define E_EX   8
#define D_DIM  4096
#define NTOT   (C_CL * E_EX)   // 64 output slots
#define MAX_T  8192
#define NSPLIT 4               // D-dim splits (1024 dims per warp)

// Scratch (no allocs allowed)
__device__ int g_cnt[C_CL];
__device__ int g_cluster[MAX_T];
__device__ int g_bucket[C_CL * MAX_T];
__device__ int g_order[MAX_T];

__global__ void zero_cnt_kernel() {
    if (threadIdx.x < C_CL) g_cnt[threadIdx.x] = 0;
}

// Read expert_ids[i] robustly whether delivered as int32 or int64.
// Content is arange(64): int32-view element 1 is 1 for int32, 0 for int64.
__device__ __forceinline__ int read_eid(const void* p, int i) {
    const int* p32 = (const int*)p;
    if (__ldg(p32 + 1) == 0) return (int)__ldg(((const long long*)p) + i);
    return __ldg(p32 + i);
}

// ---- packed f32x2 helpers (Blackwell FFMA2 only reachable via PTX) ----
__device__ __forceinline__ unsigned long long fma2(unsigned long long a,
                                                   unsigned long long b,
                                                   unsigned long long c) {
    unsigned long long d;
    asm("fma.rn.f32x2 %0, %1, %2, %3;" : "=l"(d) : "l"(a), "l"(b), "l"(c));
    return d;
}
__device__ __forceinline__ unsigned long long add2(unsigned long long a,
                                                   unsigned long long b) {
    unsigned long long d;
    asm("add.rn.f32x2 %0, %1, %2;" : "=l"(d) : "l"(a), "l"(b));
    return d;
}
__device__ __forceinline__ float sum2(unsigned long long v) {
    return __uint_as_float((unsigned)(v & 0xffffffffull)) +
           __uint_as_float((unsigned)(v >> 32));
}

// ============================================================================
// Pass A: cluster logits + argmax + bucket scatter.
// Block = 8 warps = 2 token-groups(8 tokens) x 4 D-splits(1024 dims).
// Warp: 8 tokens as two quads (A,B); weights loaded once per k-iter into
// registers, FMA'd against both quads (halves L1 weight wavefronts/token).
// ============================================================================
__global__ void __launch_bounds__(256, 2) cluster_kernel(
    const float* __restrict__ x,
    const float* __restrict__ Wc)
{
    __shared__ float s_part[2][NSPLIT][8][8];   // [tgl][split][tok_local][c]

    const int w    = threadIdx.x >> 5;
    const int lane = threadIdx.x & 31;
    const int tgl  = w >> 2;            // token-group within block (0..1)
    const int s    = w & 3;             // D-split (0..3)
    const int sub  = lane & 7;          // 16B slice within 128B line
    const int tq   = lane >> 3;         // quad index (0..3)
    const int tbase = blockIdx.x * 16 + tgl * 8;
    const int tokA = tbase + tq;
    const int tokB = tbase + 4 + tq;

    const ulonglong2* xrA = reinterpret_cast<const ulonglong2*>(x + (size_t)tokA * D_DIM);
    const ulonglong2* xrB = reinterpret_cast<const ulonglong2*>(x + (size_t)tokB * D_DIM);
    const int base = s * 256;           // float4/ulonglong2 offset of this split

    unsigned long long accA[C_CL], accB[C_CL];
#pragma unroll
    for (int c = 0; c < C_CL; ++c) { accA[c] = 0ull; accB[c] = 0ull; }

#pragma unroll 2
    for (int k = 0; k < 32; ++k) {
        const int f4 = base + k * 8 + sub;
        ulonglong2 xa = __ldg(xrA + f4);
        ulonglong2 xb = __ldg(xrB + f4);
#pragma unroll
        for (int c = 0; c < C_CL; ++c) {
            ulonglong2 wv = __ldg(reinterpret_cast<const ulonglong2*>(Wc + c * D_DIM) + f4);
            accA[c] = fma2(xa.x, wv.x, accA[c]);
            accA[c] = fma2(xa.y, wv.y, accA[c]);
            accB[c] = fma2(xb.x, wv.x, accB[c]);
            accB[c] = fma2(xb.y, wv.y, accB[c]);
        }
    }

    // Reduce across the 8 lanes of each quad.
#pragma unroll
    for (int d = 1; d <= 4; d <<= 1)
#pragma unroll
        for (int c = 0; c < C_CL; ++c) {
            accA[c] = add2(accA[c], __shfl_xor_sync(0xffffffffu, accA[c], d));
            accB[c] = add2(accB[c], __shfl_xor_sync(0xffffffffu, accB[c], d));
        }

#pragma unroll
    for (int c = 0; c < C_CL; ++c)
        if (sub == c) {
            s_part[tgl][s][tq][c]     = sum2(accA[c]);
            s_part[tgl][s][4 + tq][c] = sum2(accB[c]);
        }
    __syncthreads();

    // Combine splits + argmax: 128 threads = 2 tg x 8 tok x 8 c.
    if (threadIdx.x < 128) {
        const int tgl2 = threadIdx.x >> 6;
        const int tl   = (threadIdx.x >> 3) & 7;
        const int c    = threadIdx.x & 7;
        float v = s_part[tgl2][0][tl][c] + s_part[tgl2][1][tl][c]
                + s_part[tgl2][2][tl][c] + s_part[tgl2][3][tl][c];
        int bi = c;
#pragma unroll
        for (int d = 1; d <= 4; d <<= 1) {
            float vo = __shfl_xor_sync(0xffffffffu, v, d);
            int   io = __shfl_xor_sync(0xffffffffu, bi, d);
            if (vo > v || (vo == v && io < bi)) { v = vo; bi = io; }  // first-max
        }
        if (c == 0) {
            const int t = blockIdx.x * 16 + tgl2 * 8 + tl;
            g_cluster[t] = bi;
            int r = atomicAdd(&g_cnt[bi], 1);
            g_bucket[bi * MAX_T + r] = t;
        }
    }
}

// ============================================================================
// Middle: compact gapped buckets into cluster-major flat order.
// ============================================================================
__global__ void __launch_bounds__(256) order_kernel() {
    __shared__ int base[C_CL];
    if (threadIdx.x == 0) {
        int b = 0;
        for (int c = 0; c < C_CL; ++c) { base[c] = b; b += g_cnt[c]; }
    }
    __syncthreads();
    for (int c = 0; c < C_CL; ++c) {
        const int n = g_cnt[c];
        const int b = base[c];
        for (int i = threadIdx.x; i < n; i += 256)
            g_order[b + i] = g_bucket[c * MAX_T + i];
    }
}

// ============================================================================
// Pass B: expert logits for the selected cluster + scatter into output row.
// Same G=2 structure. Fast path (warp-uniform: every lane's two tokens share
// a cluster, ~99.7% of warps) reuses weight registers across both quads.
// ============================================================================
__global__ void __launch_bounds__(256, 2) expert_kernel(
    const float* __restrict__ x,
    const float* __restrict__ We,
    const void* __restrict__ eids,
    float* __restrict__ out)
{
    __shared__ float s_part[2][NSPLIT][8][8];   // [tgl][split][tok_local][e]
    __shared__ float s_logit[16][8];
    __shared__ int   s_eid[16][8];
    __shared__ int   s_tok[16];
    __shared__ int   s_cl[16];

    const int w    = threadIdx.x >> 5;
    const int lane = threadIdx.x & 31;
    const int tgl  = w >> 2;
    const int s    = w & 3;
    const int sub  = lane & 7;
    const int tq   = lane >> 3;
    const int pbase = blockIdx.x * 16 + tgl * 8;

    const int tokA = __ldg(&g_order[pbase + tq]);
    const int tokB = __ldg(&g_order[pbase + 4 + tq]);
    const int cA   = g_cluster[tokA];
    const int cB   = g_cluster[tokB];
    if (s == 0 && sub == 0) {
        s_tok[tgl * 8 + tq]     = tokA;  s_cl[tgl * 8 + tq]     = cA;
        s_tok[tgl * 8 + 4 + tq] = tokB;  s_cl[tgl * 8 + 4 + tq] = cB;
    }

    const ulonglong2* xrA = reinterpret_cast<const ulonglong2*>(x + (size_t)tokA * D_DIM);
    const ulonglong2* xrB = reinterpret_cast<const ulonglong2*>(x + (size_t)tokB * D_DIM);
    const float* wbA = We + (size_t)cA * (E_EX * D_DIM);
    const float* wbB = We + (size_t)cB * (E_EX * D_DIM);
    const int base = s * 256;

    unsigned long long accA[E_EX], accB[E_EX];
#pragma unroll
    for (int e = 0; e < E_EX; ++e) { accA[e] = 0ull; accB[e] = 0ull; }

    if (__all_sync(0xffffffffu, cA == cB)) {
        // Fast path: shared weight registers for both quads.
#pragma unroll 2
        for (int k = 0; k < 32; ++k) {
            const int f4 = base + k * 8 + sub;
            ulonglong2 xa = __ldg(xrA + f4);
            ulonglong2 xb = __ldg(xrB + f4);
#pragma unroll
            for (int e = 0; e < E_EX; ++e) {
                ulonglong2 wv = __ldg(reinterpret_cast<const ulonglong2*>(wbA + e * D_DIM) + f4);
                accA[e] = fma2(xa.x, wv.x, accA[e]);
                accA[e] = fma2(xa.y, wv.y, accA[e]);
                accB[e] = fma2(xb.x, wv.x, accB[e]);
                accB[e] = fma2(xb.y, wv.y, accB[e]);
            }
        }
    } else {
        // Slow path (cluster-boundary warps): per-quad weight loads.
#pragma unroll 2
        for (int k = 0; k < 32; ++k) {
            const int f4 = base + k * 8 + sub;
            ulonglong2 xa = __ldg(xrA + f4);
            ulonglong2 xb = __ldg(xrB + f4);
#pragma unroll
            for (int e = 0; e < E_EX; ++e) {
                ulonglong2 wa = __ldg(reinterpret_cast<const ulonglong2*>(wbA + e * D_DIM) + f4);
                ulonglong2 wb2 = __ldg(reinterpret_cast<const ulonglong2*>(wbB + e * D_DIM) + f4);
                accA[e] = fma2(xa.x, wa.x, accA[e]);
                accA[e] = fma2(xa.y, wa.y, accA[e]);
                accB[e] = fma2(xb.x, wb2.x, accB[e]);
                accB[e] = fma2(xb.y, wb2.y, accB[e]);
            }
        }
    }

#pragma unroll
    for (int d = 1; d <= 4; d <<= 1)
#pragma unroll
        for (int e = 0; e < E_EX; ++e) {
            accA[e] = add2(accA[e], __shfl_xor_sync(0xffffffffu, accA[e], d));
            accB[e] = add2(accB[e], __shfl_xor_sync(0xffffffffu, accB[e], d));
        }

#pragma unroll
    for (int e = 0; e < E_EX; ++e)
        if (sub == e) {
            s_part[tgl][s][tq][e]     = sum2(accA[e]);
            s_part[tgl][s][4 + tq][e] = sum2(accB[e]);
        }
    __syncthreads();

    // Combine splits + fetch expert ids: 128 threads = 16 tok x 8 e.
    if (threadIdx.x < 128) {
        const int tl2 = threadIdx.x >> 3;
        const int e   = threadIdx.x & 7;
        const int tgl2 = tl2 >> 3, tli = tl2 & 7;
        s_logit[tl2][e] = s_part[tgl2][0][tli][e] + s_part[tgl2][1][tli][e]
                        + s_part[tgl2][2][tli][e] + s_part[tgl2][3][tli][e];
        s_eid[tl2][e] = read_eid(eids, s_cl[tl2] * E_EX + e);
    }
    __syncthreads();

    // Scatter: 256 threads = 16 tokens x 16 float4 (full 64-col rows).
    {
        const int tl3 = threadIdx.x >> 4;
        const int q   = threadIdx.x & 15;
        const int tok3 = s_tok[tl3];
        float v[4];
#pragma unroll
        for (int j = 0; j < 4; ++j) {
            const int col = q * 4 + j;
            float val = -FLT_MAX;              // == jnp.finfo(float32).min
#pragma unroll
            for (int e = 0; e < E_EX; ++e)
                val = (s_eid[tl3][e] == col) ? s_logit[tl3][e] : val;
            v[j] = val;
        }
        reinterpret_cast<float4*>(out + (size_t)tok3 * NTOT)[q] =
            make_float4(v[0], v[1], v[2], v[3]);
    }
}

extern "C" void kernel_launch(void* const* d_in, const int* in_sizes, int n_in,
                              void* d_out, int out_size) {
    const float* x    = (const float*)d_in[0];
    const float* Wc   = (const float*)d_in[1];
    const float* We   = (const float*)d_in[2];
    const void*  eids = d_in[3];
    float*       out  = (float*)d_out;

    const int D = in_sizes[2] / in_sizes[3];     // 4096
    const int T = in_sizes[0] / D;               // 8192
    (void)n_in; (void)out_size;

    zero_cnt_kernel<<<1, 32>>>();

    const int blocks = T / 16;           // 16 tokens per block
    cluster_kernel<<<blocks, 256>>>(x, Wc);
    order_kernel<<<1, 256>>>();
    expert_kernel<<<blocks, 256>>>(x, We, eids, out);
}